// round 15
// baseline (speedup 1.0000x reference)
#include <cuda_runtime.h>
#include <math.h>

#define BB 2
#define S1D 64
#define S2D 64
#define S3D 40
#define CHW 64
#define MMD 23
#define TTD 8
#define NPTS (BB*S1D*S2D*S3D)   // 327680
#define NLAY 4

// ---------------- device scratch ----------------
__device__ __align__(16) float g_x [NPTS*CHW];
__device__ __align__(16) float g_Ar[BB*S1D*S2D*TTD*CHW];
__device__ __align__(16) float g_Ai[BB*S1D*S2D*TTD*CHW];
__device__ __align__(16) float g_Br[BB*MMD*S2D*TTD*CHW];
__device__ __align__(16) float g_Bi[BB*MMD*S2D*TTD*CHW];
__device__ __align__(16) float g_Xr[BB*MMD*MMD*TTD*CHW];
__device__ __align__(16) float g_Xi[BB*MMD*MMD*TTD*CHW];
__device__ __align__(16) float g_Yr[BB*MMD*MMD*TTD*CHW];
__device__ __align__(16) float g_Yi[BB*MMD*MMD*TTD*CHW];
__device__ __align__(16) float g_wlc[NLAY*12*TTD*CHW*CHW];
__device__ __align__(16) float g_wlr[NLAY*11*11*TTD*CHW*CHW];

// twiddles
__device__ __align__(16) float t_fz[S3D][16];
__device__ __align__(16) float t_iz[S3D][16];
__device__ __align__(16) float t_fy[S1D][48];
__device__ __align__(16) float t_iy[MMD][128];

__device__ __forceinline__ float4 f4fma(float4 a, float s, float4 acc) {
    acc.x = fmaf(a.x, s, acc.x); acc.y = fmaf(a.y, s, acc.y);
    acc.z = fmaf(a.z, s, acc.z); acc.w = fmaf(a.w, s, acc.w);
    return acc;
}
__device__ __forceinline__ float4 f4zero() { return make_float4(0.f, 0.f, 0.f, 0.f); }

__device__ __forceinline__ float gelu_exact(float z) {
    return 0.5f * z * (1.0f + erff(z * 0.70710678118654752f));
}

// ---- tf32 helpers (3xTF32 split GEMM) ----
__device__ __forceinline__ unsigned tf32_hi(float x) {
    unsigned r; asm("cvt.rna.tf32.f32 %0, %1;" : "=r"(r) : "f"(x)); return r;
}
__device__ __forceinline__ void mma_tf32(float* d, const unsigned* a, const unsigned* b) {
    asm volatile("mma.sync.aligned.m16n8k8.row.col.f32.tf32.tf32.f32 "
        "{%0,%1,%2,%3}, {%4,%5,%6,%7}, {%8,%9}, {%0,%1,%2,%3};"
        : "+f"(d[0]), "+f"(d[1]), "+f"(d[2]), "+f"(d[3])
        : "r"(a[0]), "r"(a[1]), "r"(a[2]), "r"(a[3]), "r"(b[0]), "r"(b[1]));
}

// ---------------- twiddle init ----------------
__global__ void init_tw_k() {
    int tid = threadIdx.x;   // 256
    for (int i = tid; i < TTD * S3D; i += 256) {
        int k = i / S3D, n = i % S3D;
        float s, c;
        sincospif((float)((2 * k * n) % 80) * (1.0f / 40.0f), &s, &c);
        t_fz[n][2 * k] = c; t_fz[n][2 * k + 1] = s;
        float sc = (k == 0 ? 1.0f : 2.0f) * (1.0f / 163840.0f);
        t_iz[n][2 * k] = c * sc; t_iz[n][2 * k + 1] = s * sc;
    }
    for (int i = tid; i < S1D * 24; i += 256) {
        int n = i / 24, ky = i % 24;
        float c = 0.f, s = 0.f;
        if (ky < MMD) {
            int t = ((ky - 11) * n) & 63;
            sincospif((float)t * (1.0f / 32.0f), &s, &c);
        }
        t_fy[n][ky] = c; t_fy[n][24 + ky] = s;
        if (ky < MMD) { t_iy[ky][n] = c; t_iy[ky][64 + n] = s; }
    }
}

// ---------------- weight transpose: [l][io][m] -> [l][m][io] ----------------
__global__ void transpose_k(const float* __restrict__ src, int rows, int cols, int which) {
    __shared__ float tile[32][33];
    float* dst = which ? g_wlr : g_wlc;
    int l = blockIdx.z;
    const float* s = src + (size_t)l * rows * cols;
    float* d = dst + (size_t)l * rows * cols;
    int c0 = blockIdx.x * 32, r0 = blockIdx.y * 32;
    int tx = threadIdx.x;
    for (int dy = threadIdx.y; dy < 32; dy += 8) {
        int r = r0 + dy, c = c0 + tx;
        if (r < rows && c < cols) tile[dy][tx] = s[(size_t)r * cols + c];
    }
    __syncthreads();
    for (int dy = threadIdx.y; dy < 32; dy += 8) {
        int c = c0 + dy, r = r0 + tx;
        if (r < rows && c < cols) d[(size_t)c * rows + r] = tile[tx][dy];
    }
}

// ---------------- lift (round-5 proven) ----------------
__global__ void lift_k(const float* __restrict__ xin, const float* __restrict__ pw,
                       const float* __restrict__ pb) {
    __shared__ float wT[13 * 64];
    __shared__ float xs[64 * 10];
    int tid = threadIdx.x;          // 256
    for (int j = tid; j < 832; j += 256) {
        int c = j / 13, i = j % 13;
        wT[i * 64 + c] = pw[j];
    }
    int p0g = blockIdx.x * 64;
    for (int j = tid; j < 640; j += 256) xs[j] = xin[(size_t)p0g * 10 + j];
    __syncthreads();

    int c0 = (tid & 15) * 4;
    float4 pb4 = *(const float4*)&pb[c0];
    float4 w10 = *(const float4*)&wT[10 * 64 + c0];
    float4 w11 = *(const float4*)&wT[11 * 64 + c0];
    float4 w12 = *(const float4*)&wT[12 * 64 + c0];
#pragma unroll
    for (int pass = 0; pass < 4; pass++) {
        int pl = pass * 16 + (tid >> 4);
        int p = p0g + pl;
        int n3 = p % S3D;
        int r = p / S3D;
        int n2 = r & 63; r >>= 6;
        int n1 = r & 63;
        float4 acc = pb4;
        acc = f4fma(w10, n1 * (1.0f / 63.0f), acc);
        acc = f4fma(w11, n2 * (1.0f / 63.0f), acc);
        acc = f4fma(w12, n3 * (1.0f / 39.0f), acc);
        const float* xp = &xs[pl * 10];
#pragma unroll
        for (int i = 0; i < 10; i++) {
            float4 wv = *(const float4*)&wT[i * 64 + c0];
            acc = f4fma(wv, xp[i], acc);
        }
        *(float4*)&g_x[(size_t)p * 64 + c0] = acc;
    }
}

// ---------------- forward z-DFT ----------------
__global__ void fwdz_k() {
    __shared__ __align__(16) float tw[S3D][16];
    int tid = threadIdx.x;  // 256
    for (int i = tid; i < S3D * 16; i += 256) tw[i >> 4][i & 15] = t_fz[i >> 4][i & 15];
    __syncthreads();
    int col = blockIdx.x * 8 + (tid >> 5);
    int lane = tid & 31;
    int cg = lane & 15, kzg = lane >> 4;
    const float4* xp = (const float4*)g_x + (size_t)col * 640 + cg;
    float4 ar[4], ai[4];
#pragma unroll
    for (int j = 0; j < 4; j++) { ar[j] = f4zero(); ai[j] = f4zero(); }
#pragma unroll 8
    for (int n = 0; n < S3D; n++) {
        float4 v = xp[n * 16];
        float4 t0 = *(const float4*)&tw[n][kzg * 8];
        float4 t1 = *(const float4*)&tw[n][kzg * 8 + 4];
        ar[0] = f4fma(v,  t0.x, ar[0]); ai[0] = f4fma(v, -t0.y, ai[0]);
        ar[1] = f4fma(v,  t0.z, ar[1]); ai[1] = f4fma(v, -t0.w, ai[1]);
        ar[2] = f4fma(v,  t1.x, ar[2]); ai[2] = f4fma(v, -t1.y, ai[2]);
        ar[3] = f4fma(v,  t1.z, ar[3]); ai[3] = f4fma(v, -t1.w, ai[3]);
    }
    float4* Ar4 = (float4*)g_Ar;
    float4* Ai4 = (float4*)g_Ai;
    size_t base = (size_t)col * 128 + kzg * 64 + cg;
#pragma unroll
    for (int j = 0; j < 4; j++) {
        Ar4[base + j * 16] = ar[j];
        Ai4[base + j * 16] = ai[j];
    }
}

// ---------------- forward y-DFT (384 threads, 1 ky/thread) ----------------
__global__ void fwdy_k() {
    __shared__ __align__(16) float Sr[S1D][CHW], Si[S1D][CHW];
    __shared__ __align__(16) float twf[S1D][48];
    int tid = threadIdx.x;  // 384
    int blk = blockIdx.x;
    int kz = blk & 7, rest = blk >> 3;
    int n2 = rest & 63, b = rest >> 6;
    const float4* Ar4 = (const float4*)g_Ar;
    const float4* Ai4 = (const float4*)g_Ai;
    for (int i = tid; i < 1024; i += 384) {
        int n1 = i >> 4, c4 = i & 15;
        size_t g4 = ((((size_t)b * S1D + n1) * S2D + n2) * TTD + kz) * 16 + c4;
        *(float4*)&Sr[n1][c4 * 4] = Ar4[g4];
        *(float4*)&Si[n1][c4 * 4] = Ai4[g4];
    }
    for (int i = tid; i < 768; i += 384) ((float4*)twf)[i] = ((const float4*)t_fy)[i];
    __syncthreads();
    int cg = tid & 15, kg = tid >> 4;   // kg 0..23, 1 ky each (kg=23 idle)
    float4 ar = f4zero(), ai = f4zero();
#pragma unroll 4
    for (int n = 0; n < S1D; n++) {
        float4 xr = *(const float4*)&Sr[n][cg * 4];
        float4 xi = *(const float4*)&Si[n][cg * 4];
        float tc = twf[n][kg];
        float ts = twf[n][24 + kg];
        ar = f4fma(xr, tc, ar); ar = f4fma(xi, ts, ar);
        ai = f4fma(xi, tc, ai); ai = f4fma(xr, -ts, ai);
    }
    if (kg < MMD) {
        size_t g4 = ((((size_t)b * MMD + kg) * S2D + n2) * TTD + kz) * 16 + cg;
        ((float4*)g_Br)[g4] = ar;
        ((float4*)g_Bi)[g4] = ai;
    }
}

// ---------------- forward x-DFT (384 threads, 1 kx/thread) ----------------
__global__ void fwdx_k() {
    __shared__ __align__(16) float Sr[S2D][CHW], Si[S2D][CHW];
    __shared__ __align__(16) float twf[S2D][48];
    int tid = threadIdx.x;  // 384
    int blk = blockIdx.x;
    int kz = blk & 7, rest = blk >> 3;
    int ky = rest % MMD, b = rest / MMD;
    const float4* Br4 = (const float4*)g_Br;
    const float4* Bi4 = (const float4*)g_Bi;
    for (int i = tid; i < 1024; i += 384) {
        int n2 = i >> 4, c4 = i & 15;
        size_t g4 = ((((size_t)b * MMD + ky) * S2D + n2) * TTD + kz) * 16 + c4;
        *(float4*)&Sr[n2][c4 * 4] = Br4[g4];
        *(float4*)&Si[n2][c4 * 4] = Bi4[g4];
    }
    for (int i = tid; i < 768; i += 384) ((float4*)twf)[i] = ((const float4*)t_fy)[i];
    __syncthreads();
    int cg = tid & 15, kg = tid >> 4;   // kg 0..23, 1 kx each (kg=23 idle)
    float4 ar = f4zero(), ai = f4zero();
#pragma unroll 4
    for (int n = 0; n < S2D; n++) {
        float4 xr = *(const float4*)&Sr[n][cg * 4];
        float4 xi = *(const float4*)&Si[n][cg * 4];
        float tc = twf[n][kg];
        float ts = twf[n][24 + kg];
        ar = f4fma(xr, tc, ar); ar = f4fma(xi, ts, ar);
        ai = f4fma(xi, tc, ai); ai = f4fma(xr, -ts, ai);
    }
    if (kg < MMD) {
        size_t g4 = ((((size_t)b * MMD + ky) * MMD + kg) * TTD + kz) * 16 + cg;
        ((float4*)g_Xr)[g4] = ar;
        ((float4*)g_Xi)[g4] = ai;
    }
}

// --------- mode -> (sel, a, b) mapping ---------
__device__ __forceinline__ void map_mode(int y, int x, int& sel, int& ia, int& ib) {
    int yy, s;
    if (x >= 11) { yy = y; s = x - 11; }
    else         { yy = 22 - y; s = 11 - x; }
    int r, t;
    if (yy < 12) {
        if (s == 0) { sel = 0; ia = 11 - yy; ib = 0; return; }
        r = s - 1; t = 11 - yy;
    } else { r = yy - 12; t = s; }
    if (t == 0) { sel = 0; ia = r + 1; ib = 0; }
    else        { sel = 1; ia = r;     ib = t - 1; }
}

// -------- per-mode mix fused with W1 (round-5 proven) --------
__global__ void mix_k(int l, const float* __restrict__ w1) {
    __shared__ __align__(16) float xs[BB][2][CHW];
    __shared__ __align__(16) float red[8][256];
    __shared__ float w1s[64 * 65];
    __shared__ float ys[256];
    int m = blockIdx.x;
    int kz = m % TTD, x = (m / TTD) % MMD, y = m / (TTD * MMD);
    int sel, ia, ib;
    map_mode(y, x, sel, ia, ib);
    const float* wp;
    if (sel == 0) wp = g_wlc + (((size_t)l * 12 + ia) * TTD + kz) * (CHW * CHW);
    else          wp = g_wlr + (((size_t)l * 121 + ia * 11 + ib) * TTD + kz) * (CHW * CHW);
    int tid = threadIdx.x;   // 128
    for (int j = tid; j < 4096; j += 128)
        w1s[(j & 63) * 65 + (j >> 6)] = w1[j];
    {
        int b = tid >> 6, c = tid & 63;
        size_t g = ((((size_t)b * MMD + y) * MMD + x) * TTD + kz) * CHW + c;
        xs[b][0][c] = g_Xr[g];
        xs[b][1][c] = g_Xi[g];
    }
    __syncthreads();
    int ks = tid >> 4, og = tid & 15;
    float4 a00 = f4zero(), a01 = f4zero(), a10 = f4zero(), a11 = f4zero();
    const float4* wp4 = (const float4*)wp;
#pragma unroll
    for (int it = 0; it < 8; it++) {
        int i = ks * 8 + it;
        float4 w = wp4[i * 16 + og];
        a00 = f4fma(w, xs[0][0][i], a00);
        a01 = f4fma(w, xs[0][1][i], a01);
        a10 = f4fma(w, xs[1][0][i], a10);
        a11 = f4fma(w, xs[1][1][i], a11);
    }
    *(float4*)&red[ks][  0 + og * 4] = a00;
    *(float4*)&red[ks][ 64 + og * 4] = a01;
    *(float4*)&red[ks][128 + og * 4] = a10;
    *(float4*)&red[ks][192 + og * 4] = a11;
    __syncthreads();
    for (int v = tid; v < 256; v += 128) {
        float s = 0.f;
#pragma unroll
        for (int k = 0; k < 8; k++) s += red[k][v];
        ys[v] = s;
    }
    __syncthreads();
    for (int v = tid; v < 256; v += 128) {
        int o = v & 63;
        int base = v & 192;
        float acc = 0.f;
#pragma unroll 8
        for (int i = 0; i < 64; i++)
            acc = fmaf(w1s[i * 65 + o], ys[base + i], acc);
        int b = v >> 7, ri = (v >> 6) & 1;
        size_t g = ((((size_t)b * MMD + y) * MMD + x) * TTD + kz) * CHW + o;
        if (ri) g_Yi[g] = acc; else g_Yr[g] = acc;
    }
}

// ---------------- inverse y (512 threads, 2 n/thread) ----------------
__global__ void invy_k() {
    __shared__ __align__(16) float Sr[MMD][CHW], Si[MMD][CHW];
    __shared__ __align__(16) float twi[MMD][128];
    int tid = threadIdx.x;  // 512
    int blk = blockIdx.x;
    int kz = blk & 7, rest = blk >> 3;
    int kx = rest % MMD, b = rest / MMD;
    const float4* Yr4 = (const float4*)g_Yr;
    const float4* Yi4 = (const float4*)g_Yi;
    if (tid < MMD * 16) {
        int ky = tid >> 4, c4 = tid & 15;
        size_t g4 = ((((size_t)b * MMD + ky) * MMD + kx) * TTD + kz) * 16 + c4;
        *(float4*)&Sr[ky][c4 * 4] = Yr4[g4];
        *(float4*)&Si[ky][c4 * 4] = Yi4[g4];
    }
    for (int i = tid; i < 736; i += 512) ((float4*)twi)[i] = ((const float4*)t_iy)[i];
    __syncthreads();
    int cg = tid & 15, ng = tid >> 4;   // ng 0..31
    int n0 = ng * 2;
    float4 ar[2], ai[2];
#pragma unroll
    for (int j = 0; j < 2; j++) { ar[j] = f4zero(); ai[j] = f4zero(); }
#pragma unroll
    for (int ky = 0; ky < MMD; ky++) {
        float4 xr = *(const float4*)&Sr[ky][cg * 4];
        float4 xi = *(const float4*)&Si[ky][cg * 4];
        float2 tc = *(const float2*)&twi[ky][n0];
        float2 ts = *(const float2*)&twi[ky][64 + n0];
        ar[0]=f4fma(xr,tc.x,ar[0]); ar[0]=f4fma(xi,-ts.x,ar[0]); ai[0]=f4fma(xr,ts.x,ai[0]); ai[0]=f4fma(xi,tc.x,ai[0]);
        ar[1]=f4fma(xr,tc.y,ar[1]); ar[1]=f4fma(xi,-ts.y,ar[1]); ai[1]=f4fma(xr,ts.y,ai[1]); ai[1]=f4fma(xi,tc.y,ai[1]);
    }
    float4* Br4 = (float4*)g_Br;
    float4* Bi4 = (float4*)g_Bi;
#pragma unroll
    for (int j = 0; j < 2; j++) {
        int n1 = n0 + j;
        size_t g4 = ((((size_t)b * S1D + n1) * MMD + kx) * TTD + kz) * 16 + cg;
        Br4[g4] = ar[j]; Bi4[g4] = ai[j];
    }
}

// ---------------- inverse x (512 threads, 2 n/thread) ----------------
__global__ void invx_k() {
    __shared__ __align__(16) float Sr[MMD][CHW], Si[MMD][CHW];
    __shared__ __align__(16) float twi[MMD][128];
    int tid = threadIdx.x;  // 512
    int blk = blockIdx.x;
    int kz = blk & 7, rest = blk >> 3;
    int n1 = rest & 63, b = rest >> 6;
    const float4* Br4 = (const float4*)g_Br;
    const float4* Bi4 = (const float4*)g_Bi;
    if (tid < MMD * 16) {
        int kx = tid >> 4, c4 = tid & 15;
        size_t g4 = ((((size_t)b * S1D + n1) * MMD + kx) * TTD + kz) * 16 + c4;
        *(float4*)&Sr[kx][c4 * 4] = Br4[g4];
        *(float4*)&Si[kx][c4 * 4] = Bi4[g4];
    }
    for (int i = tid; i < 736; i += 512) ((float4*)twi)[i] = ((const float4*)t_iy)[i];
    __syncthreads();
    int cg = tid & 15, ng = tid >> 4;   // ng 0..31
    int n0 = ng * 2;
    float4 ar[2], ai[2];
#pragma unroll
    for (int j = 0; j < 2; j++) { ar[j] = f4zero(); ai[j] = f4zero(); }
#pragma unroll
    for (int kx = 0; kx < MMD; kx++) {
        float4 xr = *(const float4*)&Sr[kx][cg * 4];
        float4 xi = *(const float4*)&Si[kx][cg * 4];
        float2 tc = *(const float2*)&twi[kx][n0];
        float2 ts = *(const float2*)&twi[kx][64 + n0];
        ar[0]=f4fma(xr,tc.x,ar[0]); ar[0]=f4fma(xi,-ts.x,ar[0]); ai[0]=f4fma(xr,ts.x,ai[0]); ai[0]=f4fma(xi,tc.x,ai[0]);
        ar[1]=f4fma(xr,tc.y,ar[1]); ar[1]=f4fma(xi,-ts.y,ar[1]); ai[1]=f4fma(xr,ts.y,ai[1]); ai[1]=f4fma(xi,tc.y,ai[1]);
    }
    float4* Ar4 = (float4*)g_Ar;
    float4* Ai4 = (float4*)g_Ai;
#pragma unroll
    for (int j = 0; j < 2; j++) {
        int n2 = n0 + j;
        size_t g4 = ((((size_t)b * S1D + n1) * S2D + n2) * TTD + kz) * 16 + cg;
        Ar4[g4] = ar[j]; Ai4[g4] = ai[j];
    }
}

// ===== fused invz + gelu + GEMM2 + skip GEMM (round-5 proven) =====
#define FUSE_SMEMF (4096*2 + 5120*2 + 2048 + 640)   // 21120 floats
__global__ void __launch_bounds__(256, 2)
fuse_k(const float* __restrict__ b1,
       const float* __restrict__ w2, const float* __restrict__ b2,
       const float* __restrict__ ww, const float* __restrict__ wb,
       int do_relu) {
    extern __shared__ float sm[];
    float* w2T = sm;
    float* wwT = sm + 4096;
    float* sX  = sm + 8192;
    float* sA  = sm + 13312;
    float* dDf = sm + 18432;
    float* tw  = sm + 20480;
    int tx = threadIdx.x & 15, ty = threadIdx.x >> 4;
    int tid = threadIdx.x;

    for (int i = tid; i < 4096; i += 256) {
        int o = i >> 6, ic = i & 63;
        w2T[ic * 64 + o] = w2[i];
        wwT[ic * 64 + o] = ww[i];
    }
    for (int i = tid; i < 640; i += 256) tw[i] = ((const float*)t_iz)[i];

    int o0 = tx * 4, q0 = ty * 5;
    float bbv[4];
#pragma unroll
    for (int s = 0; s < 4; s++) bbv[s] = b2[o0 + s] + wb[o0 + s];
    float4 b1c = *(const float4*)&b1[(tid & 15) * 4];
    __syncthreads();

    const float4* Ar4 = (const float4*)g_Ar;
    const float4* Ai4 = (const float4*)g_Ai;
    float4* dD = (float4*)dDf;

    for (int pair = blockIdx.x; pair < 4096; pair += gridDim.x) {
        size_t pbase = (size_t)pair * 80;
        size_t colg = (size_t)pair * 2;
        dD[tid]       = Ar4[colg * 128 + tid];
        dD[256 + tid] = Ai4[colg * 128 + tid];
        {
            const float4* gx4 = (const float4*)g_x + pbase * 16;
            float4* sX4 = (float4*)sX;
#pragma unroll
            for (int i = 0; i < 5; i++) sX4[tid + i * 256] = gx4[tid + i * 256];
        }
        __syncthreads();

        {
            int cg = tid & 15, rg = tid >> 4;
            int ccprev = -1;
            float4 dr[8], di[8];
#pragma unroll
            for (int r = 0; r < 5; r++) {
                int row = rg * 5 + r;
                int cc = (row >= 40) ? 1 : 0;
                int n3 = row - cc * 40;
                if (cc != ccprev) {
#pragma unroll
                    for (int k = 0; k < 8; k++) {
                        dr[k] = dD[cc * 128 + k * 16 + cg];
                        di[k] = dD[256 + cc * 128 + k * 16 + cg];
                    }
                    ccprev = cc;
                }
                float4 t0 = *(const float4*)&tw[n3 * 16 + 0];
                float4 t1 = *(const float4*)&tw[n3 * 16 + 4];
                float4 t2 = *(const float4*)&tw[n3 * 16 + 8];
                float4 t3 = *(const float4*)&tw[n3 * 16 + 12];
                float4 acc = f4zero();
                acc = f4fma(dr[0],  t0.x, acc); acc = f4fma(di[0], -t0.y, acc);
                acc = f4fma(dr[1],  t0.z, acc); acc = f4fma(di[1], -t0.w, acc);
                acc = f4fma(dr[2],  t1.x, acc); acc = f4fma(di[2], -t1.y, acc);
                acc = f4fma(dr[3],  t1.z, acc); acc = f4fma(di[3], -t1.w, acc);
                acc = f4fma(dr[4],  t2.x, acc); acc = f4fma(di[4], -t2.y, acc);
                acc = f4fma(dr[5],  t2.z, acc); acc = f4fma(di[5], -t2.w, acc);
                acc = f4fma(dr[6],  t3.x, acc); acc = f4fma(di[6], -t3.y, acc);
                acc = f4fma(dr[7],  t3.z, acc); acc = f4fma(di[7], -t3.w, acc);
                float4 h;
                h.x = gelu_exact(acc.x + b1c.x);
                h.y = gelu_exact(acc.y + b1c.y);
                h.z = gelu_exact(acc.z + b1c.z);
                h.w = gelu_exact(acc.w + b1c.w);
                *(float4*)&sA[row * 64 + cg * 4] = h;
            }
        }
        __syncthreads();

        float acc[5][4];
#pragma unroll
        for (int r = 0; r < 5; r++)
#pragma unroll
            for (int s = 0; s < 4; s++) acc[r][s] = 0.f;
#pragma unroll 4
        for (int ic = 0; ic < 64; ic += 4) {
            float a[5][4];
#pragma unroll
            for (int r = 0; r < 5; r++) {
                float4 t = *(const float4*)&sA[(q0 + r) * 64 + ic];
                a[r][0] = t.x; a[r][1] = t.y; a[r][2] = t.z; a[r][3] = t.w;
            }
#pragma unroll
            for (int kk = 0; kk < 4; kk++) {
                float4 w = *(const float4*)&w2T[(ic + kk) * 64 + o0];
#pragma unroll
                for (int r = 0; r < 5; r++) {
                    acc[r][0] = fmaf(a[r][kk], w.x, acc[r][0]);
                    acc[r][1] = fmaf(a[r][kk], w.y, acc[r][1]);
                    acc[r][2] = fmaf(a[r][kk], w.z, acc[r][2]);
                    acc[r][3] = fmaf(a[r][kk], w.w, acc[r][3]);
                }
            }
        }
#pragma unroll 4
        for (int ic = 0; ic < 64; ic += 4) {
            float a[5][4];
#pragma unroll
            for (int r = 0; r < 5; r++) {
                float4 t = *(const float4*)&sX[(q0 + r) * 64 + ic];
                a[r][0] = t.x; a[r][1] = t.y; a[r][2] = t.z; a[r][3] = t.w;
            }
#pragma unroll
            for (int kk = 0; kk < 4; kk++) {
                float4 w = *(const float4*)&wwT[(ic + kk) * 64 + o0];
#pragma unroll
                for (int r = 0; r < 5; r++) {
                    acc[r][0] = fmaf(a[r][kk], w.x, acc[r][0]);
                    acc[r][1] = fmaf(a[r][kk], w.y, acc[r][1]);
                    acc[r][2] = fmaf(a[r][kk], w.z, acc[r][2]);
                    acc[r][3] = fmaf(a[r][kk], w.w, acc[r][3]);
                }
            }
        }
#pragma unroll
        for (int r = 0; r < 5; r++) {
            float4 v;
            v.x = acc[r][0] + bbv[0]; v.y = acc[r][1] + bbv[1];
            v.z = acc[r][2] + bbv[2]; v.w = acc[r][3] + bbv[3];
            if (do_relu) {
                v.x = fmaxf(v.x, 0.f); v.y = fmaxf(v.y, 0.f);
                v.z = fmaxf(v.z, 0.f); v.w = fmaxf(v.w, 0.f);
            }
            *(float4*)&g_x[(pbase + q0 + r) * 64 + o0] = v;
        }
        __syncthreads();
    }
}

// ===== query MLP via 3xTF32 mma.sync (round-9 proven champion) =====
#define QMLP_SMEMF (16896*2 + 4352 + 256 + 256 + 128)   // 38784 floats = 155136 B
__global__ void __launch_bounds__(256, 1)
qmlp_k(const float* __restrict__ w1, const float* __restrict__ b1,
       const float* __restrict__ w2, const float* __restrict__ b2,
       float* __restrict__ out) {
    extern __shared__ float sm[];
    float* w1hi = sm;                  // [k][264]
    float* w1lo = sm + 16896;
    float* sx   = sm + 33792;          // [p][68]
    float* sb1  = sm + 38144;
    float* sw2  = sm + 38400;
    float* spart= sm + 38656;          // [2][64]
    int tid = threadIdx.x;
    int lane = tid & 31, warp = tid >> 5;
    int grp = lane >> 2, qd = lane & 3;
    int mrow = (warp & 3) * 16;
    int half = warp >> 2;
    int nbase = half * 128;

    for (int i = tid; i < 16384; i += 256) {
        int j = i >> 6, k = i & 63;
        float v = w1[i];
        unsigned hi = tf32_hi(v);
        float lo = v - __uint_as_float(hi);
        w1hi[k * 264 + j] = __uint_as_float(hi);
        w1lo[k * 264 + j] = __uint_as_float(tf32_hi(lo));
    }
    sb1[tid] = b1[tid];
    sw2[tid] = w2[tid];
    __syncthreads();
    float qb = b2[0];

    for (int tile = blockIdx.x; tile < NPTS / 64; tile += gridDim.x) {
        size_t p0g = (size_t)tile * 64;
        {
            const float4* x4 = (const float4*)g_x + p0g * 16;
            for (int i4 = tid; i4 < 1024; i4 += 256) {
                int p = i4 >> 4, k4 = i4 & 15;
                *(float4*)&sx[p * 68 + k4 * 4] = x4[i4];
            }
        }
        __syncthreads();

        float acc[16][4];
#pragma unroll
        for (int t = 0; t < 16; t++)
#pragma unroll
            for (int s = 0; s < 4; s++) acc[t][s] = 0.f;

#pragma unroll
        for (int kk = 0; kk < 8; kk++) {
            int k0 = kk * 8;
            float x0 = sx[(mrow + grp) * 68 + k0 + qd];
            float x1 = sx[(mrow + 8 + grp) * 68 + k0 + qd];
            float x2 = sx[(mrow + grp) * 68 + k0 + 4 + qd];
            float x3 = sx[(mrow + 8 + grp) * 68 + k0 + 4 + qd];
            unsigned ahi[4], alo[4];
            ahi[0] = tf32_hi(x0); alo[0] = tf32_hi(x0 - __uint_as_float(ahi[0]));
            ahi[1] = tf32_hi(x1); alo[1] = tf32_hi(x1 - __uint_as_float(ahi[1]));
            ahi[2] = tf32_hi(x2); alo[2] = tf32_hi(x2 - __uint_as_float(ahi[2]));
            ahi[3] = tf32_hi(x3); alo[3] = tf32_hi(x3 - __uint_as_float(ahi[3]));
#pragma unroll
            for (int t = 0; t < 16; t++) {
                int n0 = nbase + t * 8 + grp;
                unsigned bh[2], bl[2];
                bh[0] = __float_as_uint(w1hi[(k0 + qd) * 264 + n0]);
                bh[1] = __float_as_uint(w1hi[(k0 + 4 + qd) * 264 + n0]);
                bl[0] = __float_as_uint(w1lo[(k0 + qd) * 264 + n0]);
                bl[1] = __float_as_uint(w1lo[(k0 + 4 + qd) * 264 + n0]);
                mma_tf32(acc[t], ahi, bh);
                mma_tf32(acc[t], ahi, bl);
                mma_tf32(acc[t], alo, bh);
            }
        }

        float po0 = 0.f, po1 = 0.f;
#pragma unroll
        for (int t = 0; t < 16; t++) {
            int j0 = nbase + t * 8 + 2 * qd;
            float bA = sb1[j0], bB = sb1[j0 + 1];
            float wA = sw2[j0], wB = sw2[j0 + 1];
            po0 += wA * gelu_exact(acc[t][0] + bA) + wB * gelu_exact(acc[t][1] + bB);
            po1 += wA * gelu_exact(acc[t][2] + bA) + wB * gelu_exact(acc[t][3] + bB);
        }
        po0 += __shfl_xor_sync(0xffffffffu, po0, 1);
        po0 += __shfl_xor_sync(0xffffffffu, po0, 2);
        po1 += __shfl_xor_sync(0xffffffffu, po1, 1);
        po1 += __shfl_xor_sync(0xffffffffu, po1, 2);
        if (qd == 0) {
            spart[half * 64 + mrow + grp] = po0;
            spart[half * 64 + mrow + 8 + grp] = po1;
        }
        __syncthreads();
        if (tid < 64) out[p0g + tid] = spart[tid] + spart[64 + tid] + qb;
        __syncthreads();
    }
}

// ---------------- host launcher ----------------
extern "C" void kernel_launch(void* const* d_in, const int* in_sizes, int n_in,
                              void* d_out, int out_size) {
    const float* x_in   = (const float*)d_in[0];
    const float* p_w    = (const float*)d_in[1];
    const float* p_b    = (const float*)d_in[2];
    const float* W_LC   = (const float*)d_in[3];
    const float* W_LR   = (const float*)d_in[4];
    const float* mlp_w1 = (const float*)d_in[5];
    const float* mlp_b1 = (const float*)d_in[6];
    const float* mlp_w2 = (const float*)d_in[7];
    const float* mlp_b2 = (const float*)d_in[8];
    const float* w_w    = (const float*)d_in[9];
    const float* w_b    = (const float*)d_in[10];
    const float* q_w1   = (const float*)d_in[11];
    const float* q_b1   = (const float*)d_in[12];
    const float* q_w2   = (const float*)d_in[13];
    const float* q_b2   = (const float*)d_in[14];
    float* out = (float*)d_out;

    const int FUSE_SMEM = FUSE_SMEMF * 4;   // 84480 B
    const int QMLP_SMEM = QMLP_SMEMF * 4;   // 155136 B
    cudaFuncSetAttribute(fuse_k, cudaFuncAttributeMaxDynamicSharedMemorySize, FUSE_SMEM);
    cudaFuncSetAttribute(qmlp_k, cudaFuncAttributeMaxDynamicSharedMemorySize, QMLP_SMEM);

    init_tw_k<<<1, 256>>>();
    transpose_k<<<dim3(3, 128, NLAY),  dim3(32, 8)>>>(W_LC, 4096, 96,  0);
    transpose_k<<<dim3(31, 128, NLAY), dim3(32, 8)>>>(W_LR, 4096, 968, 1);

    lift_k<<<NPTS / 64, 256>>>(x_in, p_w, p_b);

    for (int l = 0; l < NLAY; l++) {
        fwdz_k<<<BB * S1D * S2D / 8, 256>>>();
        fwdy_k<<<BB * S2D * TTD, 384>>>();
        fwdx_k<<<BB * MMD * TTD, 384>>>();
        mix_k <<<MMD * MMD * TTD, 128>>>(l, mlp_w1 + l * 4096);
        invy_k<<<BB * MMD * TTD, 512>>>();
        invx_k<<<BB * S1D * TTD, 512>>>();
        fuse_k<<<592, 256, FUSE_SMEM>>>(
            mlp_b1 + l * 64,
            mlp_w2 + l * 4096, mlp_b2 + l * 64,
            w_w + l * 4096,    w_b + l * 64,
            (l < NLAY - 1) ? 1 : 0);
    }

    qmlp_k<<<148, 256, QMLP_SMEM>>>(q_w1, q_b1, q_w2, q_b2, out);
}

// round 16
// speedup vs baseline: 1.0367x; 1.0367x over previous
#include <cuda_runtime.h>
#include <math.h>

#define BB 2
#define S1D 64
#define S2D 64
#define S3D 40
#define CHW 64
#define MMD 23
#define TTD 8
#define NPTS (BB*S1D*S2D*S3D)   // 327680
#define NLAY 4

// ---------------- device scratch ----------------
__device__ __align__(16) float g_x [NPTS*CHW];
__device__ __align__(16) float g_Ar[BB*S1D*S2D*TTD*CHW];
__device__ __align__(16) float g_Ai[BB*S1D*S2D*TTD*CHW];
__device__ __align__(16) float g_Br[BB*MMD*S2D*TTD*CHW];
__device__ __align__(16) float g_Bi[BB*MMD*S2D*TTD*CHW];
__device__ __align__(16) float g_Xr[BB*MMD*MMD*TTD*CHW];
__device__ __align__(16) float g_Xi[BB*MMD*MMD*TTD*CHW];
__device__ __align__(16) float g_Yr[BB*MMD*MMD*TTD*CHW];
__device__ __align__(16) float g_Yi[BB*MMD*MMD*TTD*CHW];
__device__ __align__(16) float g_wlc[NLAY*12*TTD*CHW*CHW];
__device__ __align__(16) float g_wlr[NLAY*11*11*TTD*CHW*CHW];

// twiddles
__device__ __align__(16) float t_fz[S3D][16];
__device__ __align__(16) float t_iz[S3D][16];
__device__ __align__(16) float t_fy[S1D][48];
__device__ __align__(16) float t_iy[MMD][128];

__device__ __forceinline__ float4 f4fma(float4 a, float s, float4 acc) {
    acc.x = fmaf(a.x, s, acc.x); acc.y = fmaf(a.y, s, acc.y);
    acc.z = fmaf(a.z, s, acc.z); acc.w = fmaf(a.w, s, acc.w);
    return acc;
}
__device__ __forceinline__ float4 f4zero() { return make_float4(0.f, 0.f, 0.f, 0.f); }

__device__ __forceinline__ float gelu_exact(float z) {
    return 0.5f * z * (1.0f + erff(z * 0.70710678118654752f));
}

// ---- tf32 helpers (3xTF32 split GEMM) ----
__device__ __forceinline__ unsigned tf32_hi(float x) {
    unsigned r; asm("cvt.rna.tf32.f32 %0, %1;" : "=r"(r) : "f"(x)); return r;
}
__device__ __forceinline__ void mma_tf32(float* d, const unsigned* a, const unsigned* b) {
    asm volatile("mma.sync.aligned.m16n8k8.row.col.f32.tf32.tf32.f32 "
        "{%0,%1,%2,%3}, {%4,%5,%6,%7}, {%8,%9}, {%0,%1,%2,%3};"
        : "+f"(d[0]), "+f"(d[1]), "+f"(d[2]), "+f"(d[3])
        : "r"(a[0]), "r"(a[1]), "r"(a[2]), "r"(a[3]), "r"(b[0]), "r"(b[1]));
}

// ---------------- twiddle init ----------------
__global__ void init_tw_k() {
    int tid = threadIdx.x;   // 256
    for (int i = tid; i < TTD * S3D; i += 256) {
        int k = i / S3D, n = i % S3D;
        float s, c;
        sincospif((float)((2 * k * n) % 80) * (1.0f / 40.0f), &s, &c);
        t_fz[n][2 * k] = c; t_fz[n][2 * k + 1] = s;
        float sc = (k == 0 ? 1.0f : 2.0f) * (1.0f / 163840.0f);
        t_iz[n][2 * k] = c * sc; t_iz[n][2 * k + 1] = s * sc;
    }
    for (int i = tid; i < S1D * 24; i += 256) {
        int n = i / 24, ky = i % 24;
        float c = 0.f, s = 0.f;
        if (ky < MMD) {
            int t = ((ky - 11) * n) & 63;
            sincospif((float)t * (1.0f / 32.0f), &s, &c);
        }
        t_fy[n][ky] = c; t_fy[n][24 + ky] = s;
        if (ky < MMD) { t_iy[ky][n] = c; t_iy[ky][64 + n] = s; }
    }
}

// ---------------- weight transpose: [l][io][m] -> [l][m][io] ----------------
__global__ void transpose_k(const float* __restrict__ src, int rows, int cols, int which) {
    __shared__ float tile[32][33];
    float* dst = which ? g_wlr : g_wlc;
    int l = blockIdx.z;
    const float* s = src + (size_t)l * rows * cols;
    float* d = dst + (size_t)l * rows * cols;
    int c0 = blockIdx.x * 32, r0 = blockIdx.y * 32;
    int tx = threadIdx.x;
    for (int dy = threadIdx.y; dy < 32; dy += 8) {
        int r = r0 + dy, c = c0 + tx;
        if (r < rows && c < cols) tile[dy][tx] = s[(size_t)r * cols + c];
    }
    __syncthreads();
    for (int dy = threadIdx.y; dy < 32; dy += 8) {
        int c = c0 + dy, r = r0 + tx;
        if (r < rows && c < cols) d[(size_t)c * rows + r] = tile[tx][dy];
    }
}

// ---------------- lift (round-5 proven) ----------------
__global__ void lift_k(const float* __restrict__ xin, const float* __restrict__ pw,
                       const float* __restrict__ pb) {
    __shared__ float wT[13 * 64];
    __shared__ float xs[64 * 10];
    int tid = threadIdx.x;          // 256
    for (int j = tid; j < 832; j += 256) {
        int c = j / 13, i = j % 13;
        wT[i * 64 + c] = pw[j];
    }
    int p0g = blockIdx.x * 64;
    for (int j = tid; j < 640; j += 256) xs[j] = xin[(size_t)p0g * 10 + j];
    __syncthreads();

    int c0 = (tid & 15) * 4;
    float4 pb4 = *(const float4*)&pb[c0];
    float4 w10 = *(const float4*)&wT[10 * 64 + c0];
    float4 w11 = *(const float4*)&wT[11 * 64 + c0];
    float4 w12 = *(const float4*)&wT[12 * 64 + c0];
#pragma unroll
    for (int pass = 0; pass < 4; pass++) {
        int pl = pass * 16 + (tid >> 4);
        int p = p0g + pl;
        int n3 = p % S3D;
        int r = p / S3D;
        int n2 = r & 63; r >>= 6;
        int n1 = r & 63;
        float4 acc = pb4;
        acc = f4fma(w10, n1 * (1.0f / 63.0f), acc);
        acc = f4fma(w11, n2 * (1.0f / 63.0f), acc);
        acc = f4fma(w12, n3 * (1.0f / 39.0f), acc);
        const float* xp = &xs[pl * 10];
#pragma unroll
        for (int i = 0; i < 10; i++) {
            float4 wv = *(const float4*)&wT[i * 64 + c0];
            acc = f4fma(wv, xp[i], acc);
        }
        *(float4*)&g_x[(size_t)p * 64 + c0] = acc;
    }
}

// ---------------- forward z-DFT ----------------
__global__ void fwdz_k() {
    __shared__ __align__(16) float tw[S3D][16];
    int tid = threadIdx.x;  // 256
    for (int i = tid; i < S3D * 16; i += 256) tw[i >> 4][i & 15] = t_fz[i >> 4][i & 15];
    __syncthreads();
    int col = blockIdx.x * 8 + (tid >> 5);
    int lane = tid & 31;
    int cg = lane & 15, kzg = lane >> 4;
    const float4* xp = (const float4*)g_x + (size_t)col * 640 + cg;
    float4 ar[4], ai[4];
#pragma unroll
    for (int j = 0; j < 4; j++) { ar[j] = f4zero(); ai[j] = f4zero(); }
#pragma unroll 8
    for (int n = 0; n < S3D; n++) {
        float4 v = xp[n * 16];
        float4 t0 = *(const float4*)&tw[n][kzg * 8];
        float4 t1 = *(const float4*)&tw[n][kzg * 8 + 4];
        ar[0] = f4fma(v,  t0.x, ar[0]); ai[0] = f4fma(v, -t0.y, ai[0]);
        ar[1] = f4fma(v,  t0.z, ar[1]); ai[1] = f4fma(v, -t0.w, ai[1]);
        ar[2] = f4fma(v,  t1.x, ar[2]); ai[2] = f4fma(v, -t1.y, ai[2]);
        ar[3] = f4fma(v,  t1.z, ar[3]); ai[3] = f4fma(v, -t1.w, ai[3]);
    }
    float4* Ar4 = (float4*)g_Ar;
    float4* Ai4 = (float4*)g_Ai;
    size_t base = (size_t)col * 128 + kzg * 64 + cg;
#pragma unroll
    for (int j = 0; j < 4; j++) {
        Ar4[base + j * 16] = ar[j];
        Ai4[base + j * 16] = ai[j];
    }
}

// ---------------- forward y-DFT (192 threads, 2 ky/thread) ----------------
__global__ void fwdy_k() {
    __shared__ __align__(16) float Sr[S1D][CHW], Si[S1D][CHW];
    __shared__ __align__(16) float twf[S1D][48];
    int tid = threadIdx.x;  // 192
    int blk = blockIdx.x;
    int kz = blk & 7, rest = blk >> 3;
    int n2 = rest & 63, b = rest >> 6;
    const float4* Ar4 = (const float4*)g_Ar;
    const float4* Ai4 = (const float4*)g_Ai;
    for (int i = tid; i < 1024; i += 192) {
        int n1 = i >> 4, c4 = i & 15;
        size_t g4 = ((((size_t)b * S1D + n1) * S2D + n2) * TTD + kz) * 16 + c4;
        *(float4*)&Sr[n1][c4 * 4] = Ar4[g4];
        *(float4*)&Si[n1][c4 * 4] = Ai4[g4];
    }
    for (int i = tid; i < 768; i += 192) ((float4*)twf)[i] = ((const float4*)t_fy)[i];
    __syncthreads();
    int cg = tid & 15, kg = tid >> 4;   // kg 0..11, 2 ky each
    float4 ar[2], ai[2];
#pragma unroll
    for (int j = 0; j < 2; j++) { ar[j] = f4zero(); ai[j] = f4zero(); }
#pragma unroll 4
    for (int n = 0; n < S1D; n++) {
        float4 xr = *(const float4*)&Sr[n][cg * 4];
        float4 xi = *(const float4*)&Si[n][cg * 4];
        float2 tc = *(const float2*)&twf[n][kg * 2];
        float2 ts = *(const float2*)&twf[n][24 + kg * 2];
        ar[0]=f4fma(xr,tc.x,ar[0]); ar[0]=f4fma(xi,ts.x,ar[0]); ai[0]=f4fma(xi,tc.x,ai[0]); ai[0]=f4fma(xr,-ts.x,ai[0]);
        ar[1]=f4fma(xr,tc.y,ar[1]); ar[1]=f4fma(xi,ts.y,ar[1]); ai[1]=f4fma(xi,tc.y,ai[1]); ai[1]=f4fma(xr,-ts.y,ai[1]);
    }
    float4* Br4 = (float4*)g_Br;
    float4* Bi4 = (float4*)g_Bi;
#pragma unroll
    for (int j = 0; j < 2; j++) {
        int ky = kg * 2 + j;
        if (ky < MMD) {
            size_t g4 = ((((size_t)b * MMD + ky) * S2D + n2) * TTD + kz) * 16 + cg;
            Br4[g4] = ar[j]; Bi4[g4] = ai[j];
        }
    }
}

// ---------------- forward x-DFT (192 threads, 2 kx/thread) ----------------
__global__ void fwdx_k() {
    __shared__ __align__(16) float Sr[S2D][CHW], Si[S2D][CHW];
    __shared__ __align__(16) float twf[S2D][48];
    int tid = threadIdx.x;  // 192
    int blk = blockIdx.x;
    int kz = blk & 7, rest = blk >> 3;
    int ky = rest % MMD, b = rest / MMD;
    const float4* Br4 = (const float4*)g_Br;
    const float4* Bi4 = (const float4*)g_Bi;
    for (int i = tid; i < 1024; i += 192) {
        int n2 = i >> 4, c4 = i & 15;
        size_t g4 = ((((size_t)b * MMD + ky) * S2D + n2) * TTD + kz) * 16 + c4;
        *(float4*)&Sr[n2][c4 * 4] = Br4[g4];
        *(float4*)&Si[n2][c4 * 4] = Bi4[g4];
    }
    for (int i = tid; i < 768; i += 192) ((float4*)twf)[i] = ((const float4*)t_fy)[i];
    __syncthreads();
    int cg = tid & 15, kg = tid >> 4;   // kg 0..11, 2 kx each
    float4 ar[2], ai[2];
#pragma unroll
    for (int j = 0; j < 2; j++) { ar[j] = f4zero(); ai[j] = f4zero(); }
#pragma unroll 4
    for (int n = 0; n < S2D; n++) {
        float4 xr = *(const float4*)&Sr[n][cg * 4];
        float4 xi = *(const float4*)&Si[n][cg * 4];
        float2 tc = *(const float2*)&twf[n][kg * 2];
        float2 ts = *(const float2*)&twf[n][24 + kg * 2];
        ar[0]=f4fma(xr,tc.x,ar[0]); ar[0]=f4fma(xi,ts.x,ar[0]); ai[0]=f4fma(xi,tc.x,ai[0]); ai[0]=f4fma(xr,-ts.x,ai[0]);
        ar[1]=f4fma(xr,tc.y,ar[1]); ar[1]=f4fma(xi,ts.y,ar[1]); ai[1]=f4fma(xi,tc.y,ai[1]); ai[1]=f4fma(xr,-ts.y,ai[1]);
    }
    float4* Xr4 = (float4*)g_Xr;
    float4* Xi4 = (float4*)g_Xi;
#pragma unroll
    for (int j = 0; j < 2; j++) {
        int kx = kg * 2 + j;
        if (kx < MMD) {
            size_t g4 = ((((size_t)b * MMD + ky) * MMD + kx) * TTD + kz) * 16 + cg;
            Xr4[g4] = ar[j]; Xi4[g4] = ai[j];
        }
    }
}

// --------- mode -> (sel, a, b) mapping ---------
__device__ __forceinline__ void map_mode(int y, int x, int& sel, int& ia, int& ib) {
    int yy, s;
    if (x >= 11) { yy = y; s = x - 11; }
    else         { yy = 22 - y; s = 11 - x; }
    int r, t;
    if (yy < 12) {
        if (s == 0) { sel = 0; ia = 11 - yy; ib = 0; return; }
        r = s - 1; t = 11 - yy;
    } else { r = yy - 12; t = s; }
    if (t == 0) { sel = 0; ia = r + 1; ib = 0; }
    else        { sel = 1; ia = r;     ib = t - 1; }
}

// -------- per-mode mix fused with W1 (round-5 proven) --------
__global__ void mix_k(int l, const float* __restrict__ w1) {
    __shared__ __align__(16) float xs[BB][2][CHW];
    __shared__ __align__(16) float red[8][256];
    __shared__ float w1s[64 * 65];
    __shared__ float ys[256];
    int m = blockIdx.x;
    int kz = m % TTD, x = (m / TTD) % MMD, y = m / (TTD * MMD);
    int sel, ia, ib;
    map_mode(y, x, sel, ia, ib);
    const float* wp;
    if (sel == 0) wp = g_wlc + (((size_t)l * 12 + ia) * TTD + kz) * (CHW * CHW);
    else          wp = g_wlr + (((size_t)l * 121 + ia * 11 + ib) * TTD + kz) * (CHW * CHW);
    int tid = threadIdx.x;   // 128
    for (int j = tid; j < 4096; j += 128)
        w1s[(j & 63) * 65 + (j >> 6)] = w1[j];
    {
        int b = tid >> 6, c = tid & 63;
        size_t g = ((((size_t)b * MMD + y) * MMD + x) * TTD + kz) * CHW + c;
        xs[b][0][c] = g_Xr[g];
        xs[b][1][c] = g_Xi[g];
    }
    __syncthreads();
    int ks = tid >> 4, og = tid & 15;
    float4 a00 = f4zero(), a01 = f4zero(), a10 = f4zero(), a11 = f4zero();
    const float4* wp4 = (const float4*)wp;
#pragma unroll
    for (int it = 0; it < 8; it++) {
        int i = ks * 8 + it;
        float4 w = wp4[i * 16 + og];
        a00 = f4fma(w, xs[0][0][i], a00);
        a01 = f4fma(w, xs[0][1][i], a01);
        a10 = f4fma(w, xs[1][0][i], a10);
        a11 = f4fma(w, xs[1][1][i], a11);
    }
    *(float4*)&red[ks][  0 + og * 4] = a00;
    *(float4*)&red[ks][ 64 + og * 4] = a01;
    *(float4*)&red[ks][128 + og * 4] = a10;
    *(float4*)&red[ks][192 + og * 4] = a11;
    __syncthreads();
    for (int v = tid; v < 256; v += 128) {
        float s = 0.f;
#pragma unroll
        for (int k = 0; k < 8; k++) s += red[k][v];
        ys[v] = s;
    }
    __syncthreads();
    for (int v = tid; v < 256; v += 128) {
        int o = v & 63;
        int base = v & 192;
        float acc = 0.f;
#pragma unroll 8
        for (int i = 0; i < 64; i++)
            acc = fmaf(w1s[i * 65 + o], ys[base + i], acc);
        int b = v >> 7, ri = (v >> 6) & 1;
        size_t g = ((((size_t)b * MMD + y) * MMD + x) * TTD + kz) * CHW + o;
        if (ri) g_Yi[g] = acc; else g_Yr[g] = acc;
    }
}

// ---------------- inverse y (256 threads, 4 n/thread) ----------------
__global__ void invy_k() {
    __shared__ __align__(16) float Sr[MMD][CHW], Si[MMD][CHW];
    __shared__ __align__(16) float twi[MMD][128];
    int tid = threadIdx.x;  // 256
    int blk = blockIdx.x;
    int kz = blk & 7, rest = blk >> 3;
    int kx = rest % MMD, b = rest / MMD;
    const float4* Yr4 = (const float4*)g_Yr;
    const float4* Yi4 = (const float4*)g_Yi;
    for (int i = tid; i < MMD * 16; i += 256) {
        int ky = i >> 4, c4 = i & 15;
        size_t g4 = ((((size_t)b * MMD + ky) * MMD + kx) * TTD + kz) * 16 + c4;
        *(float4*)&Sr[ky][c4 * 4] = Yr4[g4];
        *(float4*)&Si[ky][c4 * 4] = Yi4[g4];
    }
    for (int i = tid; i < 736; i += 256) ((float4*)twi)[i] = ((const float4*)t_iy)[i];
    __syncthreads();
    int cg = tid & 15, ng = tid >> 4;
    int n0 = ng * 4;
    float4 ar[4], ai[4];
#pragma unroll
    for (int j = 0; j < 4; j++) { ar[j] = f4zero(); ai[j] = f4zero(); }
#pragma unroll
    for (int ky = 0; ky < MMD; ky++) {
        float4 xr = *(const float4*)&Sr[ky][cg * 4];
        float4 xi = *(const float4*)&Si[ky][cg * 4];
        float4 tc = *(const float4*)&twi[ky][n0];
        float4 ts = *(const float4*)&twi[ky][64 + n0];
        ar[0]=f4fma(xr,tc.x,ar[0]); ar[0]=f4fma(xi,-ts.x,ar[0]); ai[0]=f4fma(xr,ts.x,ai[0]); ai[0]=f4fma(xi,tc.x,ai[0]);
        ar[1]=f4fma(xr,tc.y,ar[1]); ar[1]=f4fma(xi,-ts.y,ar[1]); ai[1]=f4fma(xr,ts.y,ai[1]); ai[1]=f4fma(xi,tc.y,ai[1]);
        ar[2]=f4fma(xr,tc.z,ar[2]); ar[2]=f4fma(xi,-ts.z,ar[2]); ai[2]=f4fma(xr,ts.z,ai[2]); ai[2]=f4fma(xi,tc.z,ai[2]);
        ar[3]=f4fma(xr,tc.w,ar[3]); ar[3]=f4fma(xi,-ts.w,ar[3]); ai[3]=f4fma(xr,ts.w,ai[3]); ai[3]=f4fma(xi,tc.w,ai[3]);
    }
    float4* Br4 = (float4*)g_Br;
    float4* Bi4 = (float4*)g_Bi;
#pragma unroll
    for (int j = 0; j < 4; j++) {
        int n1 = n0 + j;
        size_t g4 = ((((size_t)b * S1D + n1) * MMD + kx) * TTD + kz) * 16 + cg;
        Br4[g4] = ar[j]; Bi4[g4] = ai[j];
    }
}

// ---------------- inverse x (256 threads, 4 n/thread) ----------------
__global__ void invx_k() {
    __shared__ __align__(16) float Sr[MMD][CHW], Si[MMD][CHW];
    __shared__ __align__(16) float twi[MMD][128];
    int tid = threadIdx.x;  // 256
    int blk = blockIdx.x;
    int kz = blk & 7, rest = blk >> 3;
    int n1 = rest & 63, b = rest >> 6;
    const float4* Br4 = (const float4*)g_Br;
    const float4* Bi4 = (const float4*)g_Bi;
    for (int i = tid; i < MMD * 16; i += 256) {
        int kx = i >> 4, c4 = i & 15;
        size_t g4 = ((((size_t)b * S1D + n1) * MMD + kx) * TTD + kz) * 16 + c4;
        *(float4*)&Sr[kx][c4 * 4] = Br4[g4];
        *(float4*)&Si[kx][c4 * 4] = Bi4[g4];
    }
    for (int i = tid; i < 736; i += 256) ((float4*)twi)[i] = ((const float4*)t_iy)[i];
    __syncthreads();
    int cg = tid & 15, ng = tid >> 4;
    int n0 = ng * 4;
    float4 ar[4], ai[4];
#pragma unroll
    for (int j = 0; j < 4; j++) { ar[j] = f4zero(); ai[j] = f4zero(); }
#pragma unroll
    for (int kx = 0; kx < MMD; kx++) {
        float4 xr = *(const float4*)&Sr[kx][cg * 4];
        float4 xi = *(const float4*)&Si[kx][cg * 4];
        float4 tc = *(const float4*)&twi[kx][n0];
        float4 ts = *(const float4*)&twi[kx][64 + n0];
        ar[0]=f4fma(xr,tc.x,ar[0]); ar[0]=f4fma(xi,-ts.x,ar[0]); ai[0]=f4fma(xr,ts.x,ai[0]); ai[0]=f4fma(xi,tc.x,ai[0]);
        ar[1]=f4fma(xr,tc.y,ar[1]); ar[1]=f4fma(xi,-ts.y,ar[1]); ai[1]=f4fma(xr,ts.y,ai[1]); ai[1]=f4fma(xi,tc.y,ai[1]);
        ar[2]=f4fma(xr,tc.z,ar[2]); ar[2]=f4fma(xi,-ts.z,ar[2]); ai[2]=f4fma(xr,ts.z,ai[2]); ai[2]=f4fma(xi,tc.z,ai[2]);
        ar[3]=f4fma(xr,tc.w,ar[3]); ar[3]=f4fma(xi,-ts.w,ar[3]); ai[3]=f4fma(xr,ts.w,ai[3]); ai[3]=f4fma(xi,tc.w,ai[3]);
    }
    float4* Ar4 = (float4*)g_Ar;
    float4* Ai4 = (float4*)g_Ai;
#pragma unroll
    for (int j = 0; j < 4; j++) {
        int n2 = n0 + j;
        size_t g4 = ((((size_t)b * S1D + n1) * S2D + n2) * TTD + kz) * 16 + cg;
        Ar4[g4] = ar[j]; Ai4[g4] = ai[j];
    }
}

// ===== fused invz + gelu + GEMM2 + skip GEMM (round-5 proven) =====
#define FUSE_SMEMF (4096*2 + 5120*2 + 2048 + 640)   // 21120 floats
__global__ void __launch_bounds__(256, 2)
fuse_k(const float* __restrict__ b1,
       const float* __restrict__ w2, const float* __restrict__ b2,
       const float* __restrict__ ww, const float* __restrict__ wb,
       int do_relu) {
    extern __shared__ float sm[];
    float* w2T = sm;
    float* wwT = sm + 4096;
    float* sX  = sm + 8192;
    float* sA  = sm + 13312;
    float* dDf = sm + 18432;
    float* tw  = sm + 20480;
    int tx = threadIdx.x & 15, ty = threadIdx.x >> 4;
    int tid = threadIdx.x;

    for (int i = tid; i < 4096; i += 256) {
        int o = i >> 6, ic = i & 63;
        w2T[ic * 64 + o] = w2[i];
        wwT[ic * 64 + o] = ww[i];
    }
    for (int i = tid; i < 640; i += 256) tw[i] = ((const float*)t_iz)[i];

    int o0 = tx * 4, q0 = ty * 5;
    float bbv[4];
#pragma unroll
    for (int s = 0; s < 4; s++) bbv[s] = b2[o0 + s] + wb[o0 + s];
    float4 b1c = *(const float4*)&b1[(tid & 15) * 4];
    __syncthreads();

    const float4* Ar4 = (const float4*)g_Ar;
    const float4* Ai4 = (const float4*)g_Ai;
    float4* dD = (float4*)dDf;

    for (int pair = blockIdx.x; pair < 4096; pair += gridDim.x) {
        size_t pbase = (size_t)pair * 80;
        size_t colg = (size_t)pair * 2;
        dD[tid]       = Ar4[colg * 128 + tid];
        dD[256 + tid] = Ai4[colg * 128 + tid];
        {
            const float4* gx4 = (const float4*)g_x + pbase * 16;
            float4* sX4 = (float4*)sX;
#pragma unroll
            for (int i = 0; i < 5; i++) sX4[tid + i * 256] = gx4[tid + i * 256];
        }
        __syncthreads();

        {
            int cg = tid & 15, rg = tid >> 4;
            int ccprev = -1;
            float4 dr[8], di[8];
#pragma unroll
            for (int r = 0; r < 5; r++) {
                int row = rg * 5 + r;
                int cc = (row >= 40) ? 1 : 0;
                int n3 = row - cc * 40;
                if (cc != ccprev) {
#pragma unroll
                    for (int k = 0; k < 8; k++) {
                        dr[k] = dD[cc * 128 + k * 16 + cg];
                        di[k] = dD[256 + cc * 128 + k * 16 + cg];
                    }
                    ccprev = cc;
                }
                float4 t0 = *(const float4*)&tw[n3 * 16 + 0];
                float4 t1 = *(const float4*)&tw[n3 * 16 + 4];
                float4 t2 = *(const float4*)&tw[n3 * 16 + 8];
                float4 t3 = *(const float4*)&tw[n3 * 16 + 12];
                float4 acc = f4zero();
                acc = f4fma(dr[0],  t0.x, acc); acc = f4fma(di[0], -t0.y, acc);
                acc = f4fma(dr[1],  t0.z, acc); acc = f4fma(di[1], -t0.w, acc);
                acc = f4fma(dr[2],  t1.x, acc); acc = f4fma(di[2], -t1.y, acc);
                acc = f4fma(dr[3],  t1.z, acc); acc = f4fma(di[3], -t1.w, acc);
                acc = f4fma(dr[4],  t2.x, acc); acc = f4fma(di[4], -t2.y, acc);
                acc = f4fma(dr[5],  t2.z, acc); acc = f4fma(di[5], -t2.w, acc);
                acc = f4fma(dr[6],  t3.x, acc); acc = f4fma(di[6], -t3.y, acc);
                acc = f4fma(dr[7],  t3.z, acc); acc = f4fma(di[7], -t3.w, acc);
                float4 h;
                h.x = gelu_exact(acc.x + b1c.x);
                h.y = gelu_exact(acc.y + b1c.y);
                h.z = gelu_exact(acc.z + b1c.z);
                h.w = gelu_exact(acc.w + b1c.w);
                *(float4*)&sA[row * 64 + cg * 4] = h;
            }
        }
        __syncthreads();

        float acc[5][4];
#pragma unroll
        for (int r = 0; r < 5; r++)
#pragma unroll
            for (int s = 0; s < 4; s++) acc[r][s] = 0.f;
#pragma unroll 4
        for (int ic = 0; ic < 64; ic += 4) {
            float a[5][4];
#pragma unroll
            for (int r = 0; r < 5; r++) {
                float4 t = *(const float4*)&sA[(q0 + r) * 64 + ic];
                a[r][0] = t.x; a[r][1] = t.y; a[r][2] = t.z; a[r][3] = t.w;
            }
#pragma unroll
            for (int kk = 0; kk < 4; kk++) {
                float4 w = *(const float4*)&w2T[(ic + kk) * 64 + o0];
#pragma unroll
                for (int r = 0; r < 5; r++) {
                    acc[r][0] = fmaf(a[r][kk], w.x, acc[r][0]);
                    acc[r][1] = fmaf(a[r][kk], w.y, acc[r][1]);
                    acc[r][2] = fmaf(a[r][kk], w.z, acc[r][2]);
                    acc[r][3] = fmaf(a[r][kk], w.w, acc[r][3]);
                }
            }
        }
#pragma unroll 4
        for (int ic = 0; ic < 64; ic += 4) {
            float a[5][4];
#pragma unroll
            for (int r = 0; r < 5; r++) {
                float4 t = *(const float4*)&sX[(q0 + r) * 64 + ic];
                a[r][0] = t.x; a[r][1] = t.y; a[r][2] = t.z; a[r][3] = t.w;
            }
#pragma unroll
            for (int kk = 0; kk < 4; kk++) {
                float4 w = *(const float4*)&wwT[(ic + kk) * 64 + o0];
#pragma unroll
                for (int r = 0; r < 5; r++) {
                    acc[r][0] = fmaf(a[r][kk], w.x, acc[r][0]);
                    acc[r][1] = fmaf(a[r][kk], w.y, acc[r][1]);
                    acc[r][2] = fmaf(a[r][kk], w.z, acc[r][2]);
                    acc[r][3] = fmaf(a[r][kk], w.w, acc[r][3]);
                }
            }
        }
#pragma unroll
        for (int r = 0; r < 5; r++) {
            float4 v;
            v.x = acc[r][0] + bbv[0]; v.y = acc[r][1] + bbv[1];
            v.z = acc[r][2] + bbv[2]; v.w = acc[r][3] + bbv[3];
            if (do_relu) {
                v.x = fmaxf(v.x, 0.f); v.y = fmaxf(v.y, 0.f);
                v.z = fmaxf(v.z, 0.f); v.w = fmaxf(v.w, 0.f);
            }
            *(float4*)&g_x[(pbase + q0 + r) * 64 + o0] = v;
        }
        __syncthreads();
    }
}

// ===== query MLP via 3xTF32 mma.sync (round-9 proven champion) =====
#define QMLP_SMEMF (16896*2 + 4352 + 256 + 256 + 128)   // 38784 floats = 155136 B
__global__ void __launch_bounds__(256, 1)
qmlp_k(const float* __restrict__ w1, const float* __restrict__ b1,
       const float* __restrict__ w2, const float* __restrict__ b2,
       float* __restrict__ out) {
    extern __shared__ float sm[];
    float* w1hi = sm;                  // [k][264]
    float* w1lo = sm + 16896;
    float* sx   = sm + 33792;          // [p][68]
    float* sb1  = sm + 38144;
    float* sw2  = sm + 38400;
    float* spart= sm + 38656;          // [2][64]
    int tid = threadIdx.x;
    int lane = tid & 31, warp = tid >> 5;
    int grp = lane >> 2, qd = lane & 3;
    int mrow = (warp & 3) * 16;
    int half = warp >> 2;
    int nbase = half * 128;

    for (int i = tid; i < 16384; i += 256) {
        int j = i >> 6, k = i & 63;
        float v = w1[i];
        unsigned hi = tf32_hi(v);
        float lo = v - __uint_as_float(hi);
        w1hi[k * 264 + j] = __uint_as_float(hi);
        w1lo[k * 264 + j] = __uint_as_float(tf32_hi(lo));
    }
    sb1[tid] = b1[tid];
    sw2[tid] = w2[tid];
    __syncthreads();
    float qb = b2[0];

    for (int tile = blockIdx.x; tile < NPTS / 64; tile += gridDim.x) {
        size_t p0g = (size_t)tile * 64;
        {
            const float4* x4 = (const float4*)g_x + p0g * 16;
            for (int i4 = tid; i4 < 1024; i4 += 256) {
                int p = i4 >> 4, k4 = i4 & 15;
                *(float4*)&sx[p * 68 + k4 * 4] = x4[i4];
            }
        }
        __syncthreads();

        float acc[16][4];
#pragma unroll
        for (int t = 0; t < 16; t++)
#pragma unroll
            for (int s = 0; s < 4; s++) acc[t][s] = 0.f;

#pragma unroll
        for (int kk = 0; kk < 8; kk++) {
            int k0 = kk * 8;
            float x0 = sx[(mrow + grp) * 68 + k0 + qd];
            float x1 = sx[(mrow + 8 + grp) * 68 + k0 + qd];
            float x2 = sx[(mrow + grp) * 68 + k0 + 4 + qd];
            float x3 = sx[(mrow + 8 + grp) * 68 + k0 + 4 + qd];
            unsigned ahi[4], alo[4];
            ahi[0] = tf32_hi(x0); alo[0] = tf32_hi(x0 - __uint_as_float(ahi[0]));
            ahi[1] = tf32_hi(x1); alo[1] = tf32_hi(x1 - __uint_as_float(ahi[1]));
            ahi[2] = tf32_hi(x2); alo[2] = tf32_hi(x2 - __uint_as_float(ahi[2]));
            ahi[3] = tf32_hi(x3); alo[3] = tf32_hi(x3 - __uint_as_float(ahi[3]));
#pragma unroll
            for (int t = 0; t < 16; t++) {
                int n0 = nbase + t * 8 + grp;
                unsigned bh[2], bl[2];
                bh[0] = __float_as_uint(w1hi[(k0 + qd) * 264 + n0]);
                bh[1] = __float_as_uint(w1hi[(k0 + 4 + qd) * 264 + n0]);
                bl[0] = __float_as_uint(w1lo[(k0 + qd) * 264 + n0]);
                bl[1] = __float_as_uint(w1lo[(k0 + 4 + qd) * 264 + n0]);
                mma_tf32(acc[t], ahi, bh);
                mma_tf32(acc[t], ahi, bl);
                mma_tf32(acc[t], alo, bh);
            }
        }

        float po0 = 0.f, po1 = 0.f;
#pragma unroll
        for (int t = 0; t < 16; t++) {
            int j0 = nbase + t * 8 + 2 * qd;
            float bA = sb1[j0], bB = sb1[j0 + 1];
            float wA = sw2[j0], wB = sw2[j0 + 1];
            po0 += wA * gelu_exact(acc[t][0] + bA) + wB * gelu_exact(acc[t][1] + bB);
            po1 += wA * gelu_exact(acc[t][2] + bA) + wB * gelu_exact(acc[t][3] + bB);
        }
        po0 += __shfl_xor_sync(0xffffffffu, po0, 1);
        po0 += __shfl_xor_sync(0xffffffffu, po0, 2);
        po1 += __shfl_xor_sync(0xffffffffu, po1, 1);
        po1 += __shfl_xor_sync(0xffffffffu, po1, 2);
        if (qd == 0) {
            spart[half * 64 + mrow + grp] = po0;
            spart[half * 64 + mrow + 8 + grp] = po1;
        }
        __syncthreads();
        if (tid < 64) out[p0g + tid] = spart[tid] + spart[64 + tid] + qb;
        __syncthreads();
    }
}

// ---------------- host launcher ----------------
extern "C" void kernel_launch(void* const* d_in, const int* in_sizes, int n_in,
                              void* d_out, int out_size) {
    const float* x_in   = (const float*)d_in[0];
    const float* p_w    = (const float*)d_in[1];
    const float* p_b    = (const float*)d_in[2];
    const float* W_LC   = (const float*)d_in[3];
    const float* W_LR   = (const float*)d_in[4];
    const float* mlp_w1 = (const float*)d_in[5];
    const float* mlp_b1 = (const float*)d_in[6];
    const float* mlp_w2 = (const float*)d_in[7];
    const float* mlp_b2 = (const float*)d_in[8];
    const float* w_w    = (const float*)d_in[9];
    const float* w_b    = (const float*)d_in[10];
    const float* q_w1   = (const float*)d_in[11];
    const float* q_b1   = (const float*)d_in[12];
    const float* q_w2   = (const float*)d_in[13];
    const float* q_b2   = (const float*)d_in[14];
    float* out = (float*)d_out;

    const int FUSE_SMEM = FUSE_SMEMF * 4;   // 84480 B
    const int QMLP_SMEM = QMLP_SMEMF * 4;   // 155136 B
    cudaFuncSetAttribute(fuse_k, cudaFuncAttributeMaxDynamicSharedMemorySize, FUSE_SMEM);
    cudaFuncSetAttribute(qmlp_k, cudaFuncAttributeMaxDynamicSharedMemorySize, QMLP_SMEM);

    init_tw_k<<<1, 256>>>();
    transpose_k<<<dim3(3, 128, NLAY),  dim3(32, 8)>>>(W_LC, 4096, 96,  0);
    transpose_k<<<dim3(31, 128, NLAY), dim3(32, 8)>>>(W_LR, 4096, 968, 1);

    lift_k<<<NPTS / 64, 256>>>(x_in, p_w, p_b);

    for (int l = 0; l < NLAY; l++) {
        fwdz_k<<<BB * S1D * S2D / 8, 256>>>();
        fwdy_k<<<BB * S2D * TTD, 192>>>();
        fwdx_k<<<BB * MMD * TTD, 192>>>();
        mix_k <<<MMD * MMD * TTD, 128>>>(l, mlp_w1 + l * 4096);
        invy_k<<<BB * MMD * TTD, 256>>>();
        invx_k<<<BB * S1D * TTD, 256>>>();
        fuse_k<<<592, 256, FUSE_SMEM>>>(
            mlp_b1 + l * 64,
            mlp_w2 + l * 4096, mlp_b2 + l * 64,
            w_w + l * 4096,    w_b + l * 64,
            (l < NLAY - 1) ? 1 : 0);
    }

    qmlp_k<<<148, 256, QMLP_SMEM>>>(q_w1, q_b1, q_w2, q_b2, out);
}